// round 9
// baseline (speedup 1.0000x reference)
#include <cuda_runtime.h>
#include <cuda_bf16.h>
#include <cstdint>

#define NTOK   16384   // B*S
#define DMODEL 256
#define NHEADS 8
#define DHID   2048    // DMODEL*NHEADS

#if defined(__CUDA_ARCH_SPECIFIC__) || defined(__CUDA_ARCH_FAMILY_SPECIFIC__)
#define HAS_TC05 1
#else
#define HAS_TC05 0
#endif

typedef __nv_bfloat16 bf16;

// ---------------- device-global scratch (allocation-free) -------------------
__device__ float g_Q [(size_t)NTOK * DHID];
__device__ float g_Kp[(size_t)NTOK * DHID];
__device__ float g_Vp[(size_t)NTOK * DHID];

// Panel-major pre-swizzled bf16 2-split operands.
// arr[(p * ROWS + row) * 64 .. +64) bf16 = one 128B SW128 row
// [b0 k(32p..32p+31) | b1 same], chunk c stored at byte ((c ^ (row&7))<<4).
__device__ bf16 g_Aq[(size_t)8  * NTOK * 64];
__device__ bf16 g_Ak[(size_t)8  * NTOK * 64];
__device__ bf16 g_Av[(size_t)8  * NTOK * 64];
__device__ bf16 g_AX[(size_t)64 * NTOK * 64];
__device__ bf16 g_Bq[(size_t)8  * DHID * 64];
__device__ bf16 g_Bk[(size_t)8  * DHID * 64];
__device__ bf16 g_Bv[(size_t)8  * DHID * 64];
__device__ bf16 g_Bo[(size_t)64 * DMODEL * 64];

__device__ int g_mask_mode;   // 0=float32, 1=int32, 2=uint8/bool

// ---------------- small PTX helpers -----------------------------------------
__device__ __forceinline__ uint32_t smem_u32(const void* p) {
    uint32_t a;
    asm("{ .reg .u64 t; cvta.to.shared.u64 t, %1; cvt.u32.u64 %0, t; }"
        : "=r"(a) : "l"(p));
    return a;
}
__device__ __forceinline__ void cp16(uint32_t dst, const void* src) {
    asm volatile("cp.async.cg.shared.global [%0], [%1], 16;" :: "r"(dst), "l"(src));
}
__device__ __forceinline__ void cp_commit() {
    asm volatile("cp.async.commit_group;" ::: "memory");
}
template <int N> __device__ __forceinline__ void cp_wait() {
    asm volatile("cp.async.wait_group %0;" :: "n"(N) : "memory");
}
__device__ __forceinline__ void mbar_init(uint32_t a, uint32_t cnt) {
    asm volatile("mbarrier.init.shared.b64 [%0], %1;" :: "r"(a), "r"(cnt) : "memory");
}
__device__ __forceinline__ void mbar_arrive(uint32_t a) {
    asm volatile("mbarrier.arrive.shared.b64 _, [%0];" :: "r"(a) : "memory");
}
__device__ __forceinline__ void mbar_wait(uint32_t a, uint32_t ph) {
    asm volatile(
        "{\n\t.reg .pred P1;\n"
        "LW%=:\n\tmbarrier.try_wait.parity.acquire.cta.shared::cta.b64 P1, [%0], %1;\n"
        "\t@P1 bra LD%=;\n\tbra LW%=;\n"
        "LD%=:\n\t}"
        :: "r"(a), "r"(ph) : "memory");
}
__device__ __forceinline__ void bar_named(int id) {
    asm volatile("bar.sync %0, 128;" :: "r"(id) : "memory");
}

// ---- tcgen05 wrappers (arch-specific pass only) -----------------------------
__device__ __forceinline__ void tc_alloc(uint32_t slot, uint32_t ncols) {
#if HAS_TC05
    asm volatile("tcgen05.alloc.cta_group::1.sync.aligned.shared::cta.b32 [%0], %1;"
                 :: "r"(slot), "r"(ncols) : "memory");
#endif
}
__device__ __forceinline__ void tc_dealloc(uint32_t tmem, uint32_t ncols) {
#if HAS_TC05
    asm volatile("tcgen05.dealloc.cta_group::1.sync.aligned.b32 %0, %1;"
                 :: "r"(tmem), "r"(ncols));
#endif
}
__device__ __forceinline__ void tc_commit(uint32_t mbar) {
#if HAS_TC05
    asm volatile("tcgen05.commit.cta_group::1.mbarrier::arrive::one.shared::cluster.b64 [%0];"
                 :: "r"(mbar) : "memory");
#else
    mbar_arrive(mbar);
#endif
}
__device__ __forceinline__ void mma_bf16(uint32_t d, uint64_t ad, uint64_t bd,
                                         uint32_t idesc, uint32_t acc) {
#if HAS_TC05
    asm volatile(
        "{\n\t.reg .pred p;\n"
        "\tsetp.ne.u32 p, %4, 0;\n"
        "\ttcgen05.mma.cta_group::1.kind::f16 [%0], %1, %2, %3, p;\n\t}"
        :: "r"(d), "l"(ad), "l"(bd), "r"(idesc), "r"(acc) : "memory");
#endif
}
__device__ __forceinline__ void ldtm32(uint32_t* r, uint32_t a) {
#if HAS_TC05
    asm volatile(
        "tcgen05.ld.sync.aligned.32x32b.x32.b32 "
        "{%0, %1, %2, %3, %4, %5, %6, %7, %8, %9, %10, %11, %12, %13, %14, %15, "
        "%16, %17, %18, %19, %20, %21, %22, %23, %24, %25, %26, %27, %28, %29, %30, %31}, [%32];"
        : "=r"(r[0]), "=r"(r[1]), "=r"(r[2]), "=r"(r[3]), "=r"(r[4]), "=r"(r[5]),
          "=r"(r[6]), "=r"(r[7]), "=r"(r[8]), "=r"(r[9]), "=r"(r[10]), "=r"(r[11]),
          "=r"(r[12]), "=r"(r[13]), "=r"(r[14]), "=r"(r[15]), "=r"(r[16]), "=r"(r[17]),
          "=r"(r[18]), "=r"(r[19]), "=r"(r[20]), "=r"(r[21]), "=r"(r[22]), "=r"(r[23]),
          "=r"(r[24]), "=r"(r[25]), "=r"(r[26]), "=r"(r[27]), "=r"(r[28]), "=r"(r[29]),
          "=r"(r[30]), "=r"(r[31])
        : "r"(a));
#else
#pragma unroll
    for (int i = 0; i < 32; i++) r[i] = 0u;
#endif
}
__device__ __forceinline__ void tc_wait_ld() {
#if HAS_TC05
    asm volatile("tcgen05.wait::ld.sync.aligned;" ::: "memory");
#endif
}
__device__ __forceinline__ void tc_fence_after() {
#if HAS_TC05
    asm volatile("tcgen05.fence::after_thread_sync;" ::: "memory");
#endif
}
__device__ __forceinline__ void tc_fence_before() {
#if HAS_TC05
    asm volatile("tcgen05.fence::before_thread_sync;" ::: "memory");
#endif
}

// SW128 K-major SMEM descriptor (LBO=1, SBO=64, version=1, layout=SW128)
__device__ __forceinline__ uint64_t mkdesc(uint32_t addr) {
    const uint64_t BASE = (2ull << 61) | (1ull << 46) | (64ull << 32) | (1ull << 16);
    return BASE | ((uint64_t)(addr >> 4) & 0x3FFF);
}

// idesc kind::f16: cF32(bit4), aBF16(bit7), bBF16(bit10), N=128 (16<<17), M=128 (8<<24)
#define IDESC_BF16 ((1u << 4) | (1u << 7) | (1u << 10) | (16u << 17) | (8u << 24))

// ---------------- persistent warp-specialized GEMM ---------------------------
// Tile job = M128 x N256.  Producer warps 0-3 stream K-panels (stage ring 3,
// cp.async identity loads of pre-swizzled panels) and issue MMAs into TMEM
// buffer job&1 (2 x 256 cols).  Consumer warps 4-7 drain finished jobs
// (LDTM + bias + SMEM transpose + coalesced STG) overlapped with the next
// job's mainloop.
struct GemmArgs {
    const bf16 *A, *B;
    const float* bias;
    float* C;
};
struct GemmArgs3 { GemmArgs g[3]; };

#define ASTAGE 16384
#define STAGE  49152
#define EPIOFF (4096 + 3 * STAGE)          // 151552
#define PERSIST_SMEM (EPIOFF + 32768)      // 184320

template <int P, int NT, int MT>
__global__ void __launch_bounds__(256, 1) gemm_persist(GemmArgs3 args, int njobs) {
    extern __shared__ __align__(1024) char smem[];
    const uint32_t sb = smem_u32(smem);
    const int tid = threadIdx.x;
    const int w = tid >> 5, lane = tid & 31;
    const int bx = blockIdx.x, gsz = gridDim.x;
    const uint32_t PD = sb + 16;    // 3 panel-done mbars
    const uint32_t JD = sb + 48;    // 2 job-done mbars
    const uint32_t BF = sb + 64;    // 2 buffer-free mbars

    if (tid == 0) {
        for (int i = 0; i < 3; i++) mbar_init(PD + i * 8, 1);
        for (int b = 0; b < 2; b++) mbar_init(JD + b * 8, 1);
        for (int b = 0; b < 2; b++) mbar_init(BF + b * 8, 128);
    }
    if (w == 0) tc_alloc(sb, 512);
    __syncthreads();
    uint32_t tmem;
    asm("ld.shared.b32 %0, [%1];" : "=r"(tmem) : "r"(sb));

    const int nj = (njobs > bx) ? (njobs - bx + gsz - 1) / gsz : 0;
    const int G = nj * P;
    const int NtotC = NT * 256;

    if (tid < 128) {
        // ---------------- producers: warps 0-3 -------------------------------
        auto load_stage = [&](int g) {
            if (g < G) {
                const int jl = g / P, p = g % P;
                const int J = bx + gsz * jl;
                const int nt = J % NT;
                const int r2 = J / NT;
                const int mt = r2 % MT, z = r2 / MT;
                const char* A = reinterpret_cast<const char*>(args.g[z].A)
                              + ((size_t)p * NTOK + (size_t)mt * 128) * 128;
                const char* B = reinterpret_cast<const char*>(args.g[z].B)
                              + ((size_t)p * NtotC + (size_t)nt * 256) * 128;
                const uint32_t st = sb + 4096 + (g % 3) * STAGE;
                const int t16 = tid << 4;
#pragma unroll
                for (int i = 0; i < 8; i++)
                    cp16(st + t16 + (i << 11), A + t16 + (i << 11));
#pragma unroll
                for (int i = 0; i < 16; i++)
                    cp16(st + ASTAGE + t16 + (i << 11), B + t16 + (i << 11));
            }
            cp_commit();
        };

        load_stage(0);
        load_stage(1);

        for (int g = 0; g < G; g++) {
            cp_wait<1>();
            asm volatile("fence.proxy.async.shared::cta;" ::: "memory");
            bar_named(1);
            const int jl = g / P, p = g % P;
            if (tid == 0) {
                if (p == 0 && jl >= 2) {
                    mbar_wait(BF + (jl & 1) * 8, ((jl - 2) >> 1) & 1);
                    tc_fence_after();
                }
                const uint32_t st = sb + 4096 + (g % 3) * STAGE;
                const uint64_t ad = mkdesc(st);
                const uint64_t bd0 = mkdesc(st + ASTAGE);
                const uint32_t tb = tmem + (jl & 1) * 256;
#pragma unroll
                for (int nh = 0; nh < 2; nh++) {
                    const uint32_t dt = tb + nh * 128;
                    const uint64_t bd = bd0 + nh * 1024;
                    mma_bf16(dt, ad + 0, bd + 0, IDESC_BF16, (p > 0) ? 1u : 0u);
                    mma_bf16(dt, ad + 2, bd + 2, IDESC_BF16, 1u);   // b0*b0
                    mma_bf16(dt, ad + 0, bd + 4, IDESC_BF16, 1u);   // b0*b1
                    mma_bf16(dt, ad + 2, bd + 6, IDESC_BF16, 1u);
                    mma_bf16(dt, ad + 4, bd + 0, IDESC_BF16, 1u);   // b1*b0
                    mma_bf16(dt, ad + 6, bd + 2, IDESC_BF16, 1u);
                }
                tc_commit(PD + (g % 3) * 8);
                if (p == P - 1) tc_commit(JD + (jl & 1) * 8);
            }
            if (g >= 1)
                mbar_wait(PD + ((g - 1) % 3) * 8, ((g - 1) / 3) & 1);
            load_stage(g + 2);
        }
    } else {
        // ---------------- consumers: warps 4-7 -------------------------------
        const int ctid = tid - 128;
        float4* eb = reinterpret_cast<float4*>(smem + EPIOFF);
        for (int jl = 0; jl < nj; jl++) {
            const int b = jl & 1;
            mbar_wait(JD + b * 8, (jl >> 1) & 1);
            tc_fence_after();
            const int J = bx + gsz * jl;
            const int nt = J % NT;
            const int r2 = J / NT;
            const int mt = r2 % MT, z = r2 / MT;
            const float* bias = args.g[z].bias + nt * 256;
            float* C = args.g[z].C + (size_t)mt * 128 * NtotC + (size_t)nt * 256;
            const int row = (w & 3) * 32 + lane;
#pragma unroll
            for (int cc = 0; cc < 4; cc++) {
                uint32_t r0[32], r1[32];
                ldtm32(r0, tmem + b * 256 + cc * 64);
                ldtm32(r1, tmem + b * 256 + cc * 64 + 32);
                tc_wait_ld();
#pragma unroll
                for (int j = 0; j < 8; j++) {
                    float4 bv = *reinterpret_cast<const float4*>(bias + cc * 64 + j * 4);
                    float4 v;
                    v.x = __uint_as_float(r0[4 * j + 0]) + bv.x;
                    v.y = __uint_as_float(r0[4 * j + 1]) + bv.y;
                    v.z = __uint_as_float(r0[4 * j + 2]) + bv.z;
                    v.w = __uint_as_float(r0[4 * j + 3]) + bv.w;
                    eb[row * 16 + (j ^ (row & 15))] = v;
                }
#pragma unroll
                for (int j = 0; j < 8; j++) {
                    float4 bv = *reinterpret_cast<const float4*>(bias + cc * 64 + 32 + j * 4);
                    float4 v;
                    v.x = __uint_as_float(r1[4 * j + 0]) + bv.x;
                    v.y = __uint_as_float(r1[4 * j + 1]) + bv.y;
                    v.z = __uint_as_float(r1[4 * j + 2]) + bv.z;
                    v.w = __uint_as_float(r1[4 * j + 3]) + bv.w;
                    eb[row * 16 + ((8 + j) ^ (row & 15))] = v;
                }
                bar_named(2);
#pragma unroll
                for (int it = 0; it < 16; it++) {
                    const int r3 = it * 8 + (ctid >> 4);
                    const int c4 = ctid & 15;
                    const float4 v = eb[r3 * 16 + (c4 ^ (r3 & 15))];
                    *reinterpret_cast<float4*>(
                        C + (size_t)r3 * NtotC + cc * 64 + c4 * 4) = v;
                }
                bar_named(2);
            }
            tc_fence_before();
            mbar_arrive(BF + b * 8);
        }
    }

    __syncthreads();
    if (w == 0) tc_dealloc(tmem, 512);
}

// ---------------- bf16 2-split + panel-swizzle writers -----------------------
__device__ __forceinline__ void split2(float x, bf16& b0, bf16& b1) {
    b0 = __float2bfloat16(x);
    b1 = __float2bfloat16(x - __bfloat162float(b0));
}
__device__ __forceinline__ void store_split4(char* base, int row, int kk,
                                             const float4& x) {
    bf16 b0[4], b1[4];
    split2(x.x, b0[0], b1[0]);
    split2(x.y, b0[1], b1[1]);
    split2(x.z, b0[2], b1[2]);
    split2(x.w, b0[3], b1[3]);
    const int c  = kk >> 3;
    const int bo = (kk & 7) * 2;
    *reinterpret_cast<uint2*>(base + ((c ^ (row & 7)) << 4) + bo) =
        *reinterpret_cast<uint2*>(b0);
    *reinterpret_cast<uint2*>(base + (((c + 4) ^ (row & 7)) << 4) + bo) =
        *reinterpret_cast<uint2*>(b1);
}

__global__ void split_inputs(const float4* __restrict__ q, const float4* __restrict__ k,
                             const float4* __restrict__ v) {
    const int i = blockIdx.x * 256 + threadIdx.x;
    const float4* s;
    bf16* dst;
    if (blockIdx.y == 0)      { s = q; dst = g_Aq; }
    else if (blockIdx.y == 1) { s = k; dst = g_Ak; }
    else                      { s = v; dst = g_Av; }
    const int r = i >> 6, j0 = (i & 63) << 2;
    const int p = j0 >> 5, kk = j0 & 31;
    char* base = reinterpret_cast<char*>(dst) + (((size_t)p * NTOK + r) << 7);
    store_split4(base, r, kk, s[i]);
}

__global__ void wsplit(const float* __restrict__ Wq, const float* __restrict__ Wk,
                       const float* __restrict__ Wv, const float* __restrict__ Wo) {
    const int z = blockIdx.z;
    const float* W; bf16* T; int K_, N_;
    if (z == 0)      { W = Wq; T = g_Bq; K_ = DMODEL; N_ = DHID; }
    else if (z == 1) { W = Wk; T = g_Bk; K_ = DMODEL; N_ = DHID; }
    else if (z == 2) { W = Wv; T = g_Bv; K_ = DMODEL; N_ = DHID; }
    else             { W = Wo; T = g_Bo; K_ = DHID;  N_ = DMODEL; }
    const int bx = blockIdx.x * 32;
    const int by = blockIdx.y * 32;
    if (bx >= N_ || by >= K_) return;
    __shared__ float t[32][33];
    const int tx = threadIdx.x, ty = threadIdx.y;
#pragma unroll
    for (int i = 0; i < 4; i++)
        t[ty + i * 8][tx] = W[(size_t)(by + ty + i * 8) * N_ + bx + tx];
    __syncthreads();
#pragma unroll
    for (int i = 0; i < 4; i++) {
        const int n = bx + ty + i * 8;
        const int kx = by + tx;
        const float x = t[tx][ty + i * 8];
        bf16 b0, b1;
        split2(x, b0, b1);
        const int p = kx >> 5, kk = kx & 31;
        const int c = kk >> 3, bo = (kk & 7) * 2;
        char* base = reinterpret_cast<char*>(T) + (((size_t)p * N_ + n) << 7);
        *reinterpret_cast<bf16*>(base + ((c ^ (n & 7)) << 4) + bo) = b0;
        *reinterpret_cast<bf16*>(base + (((c + 4) ^ (n & 7)) << 4) + bo) = b1;
    }
}

__global__ void mask_probe(const unsigned char* __restrict__ m) {
    int lane = threadIdx.x;
    int big = 0, nzoff = 0;
    for (int i = lane; i < 1024; i += 32) {
        unsigned char v = m[i];
        if (v > 1) big = 1;
        if ((i & 3) != 0 && v != 0) nzoff = 1;
    }
    big   = __any_sync(0xffffffffu, big);
    nzoff = __any_sync(0xffffffffu, nzoff);
    if (lane == 0) g_mask_mode = big ? 0 : (nzoff ? 2 : 1);
}

// ---------------- per-token cross-head attention -----------------------------
__global__ void __launch_bounds__(256) attn_kernel(const void* __restrict__ maskp) {
    __shared__ __align__(16) float sq[DHID];
    __shared__ __align__(16) float sk[DHID];
    __shared__ __align__(16) float sv[DHID];
    __shared__ float sp[64];

    const int t   = blockIdx.x;
    const int tid = threadIdx.x;

    const float4* q4 = reinterpret_cast<const float4*>(g_Q  + (size_t)t * DHID);
    const float4* k4 = reinterpret_cast<const float4*>(g_Kp + (size_t)t * DHID);
    const float4* v4 = reinterpret_cast<const float4*>(g_Vp + (size_t)t * DHID);
#pragma unroll
    for (int i = 0; i < 2; i++) {
        int s = tid + i * 256;
        reinterpret_cast<float4*>(sq)[s] = q4[s];
        reinterpret_cast<float4*>(sk)[s] = k4[s];
        reinterpret_cast<float4*>(sv)[s] = v4[s];
    }
    __syncthreads();

    const int w = tid >> 5, lane = tid & 31;
#pragma unroll
    for (int j = 0; j < 8; j++) {
        int p = w * 8 + j;
        int h = p >> 3, g = p & 7;
        const float* qh = sq + h * 256 + lane;
        const float* kg = sk + g * 256 + lane;
        float s = 0.f;
#pragma unroll
        for (int i = 0; i < 8; i++) s += qh[i * 32] * kg[i * 32];
#pragma unroll
        for (int o = 16; o > 0; o >>= 1) s += __shfl_xor_sync(0xffffffffu, s, o);
        if (lane == 0) sp[p] = s * 0.0625f;
    }
    __syncthreads();

    if (tid < 8) {
        bool mv;
        int mode = g_mask_mode;
        if (mode == 0)      mv = reinterpret_cast<const float*>(maskp)[t] != 0.0f;
        else if (mode == 1) mv = reinterpret_cast<const int*>(maskp)[t] != 0;
        else                mv = reinterpret_cast<const unsigned char*>(maskp)[t] != 0;
        float l[8];
        float mx = -3.4e38f;
#pragma unroll
        for (int g = 0; g < 8; g++) {
            l[g] = mv ? sp[tid * 8 + g] : -1.0e9f;
            mx = fmaxf(mx, l[g]);
        }
        float sum = 0.f;
#pragma unroll
        for (int g = 0; g < 8; g++) { l[g] = expf(l[g] - mx); sum += l[g]; }
        float inv = 1.0f / sum;
#pragma unroll
        for (int g = 0; g < 8; g++) sp[tid * 8 + g] = l[g] * inv;
    }
    __syncthreads();

    const int b = t >> 11, sIdx = t & 2047;
    const int h = tid >> 5;
    float pw[8];
#pragma unroll
    for (int g = 0; g < 8; g++) pw[g] = sp[h * 8 + g];
    const int ar = b * 2048 + h * 256 + (sIdx >> 3);
#pragma unroll
    for (int half = 0; half < 2; half++) {
        int d = half * 128 + lane * 4;
        float4 accv = make_float4(0.f, 0.f, 0.f, 0.f);
#pragma unroll
        for (int g = 0; g < 8; g++) {
            float4 vv = *reinterpret_cast<const float4*>(sv + g * 256 + d);
            accv.x += pw[g] * vv.x;
            accv.y += pw[g] * vv.y;
            accv.z += pw[g] * vv.z;
            accv.w += pw[g] * vv.w;
        }
        const int kidx = (sIdx & 7) * 256 + d;
        const int p = kidx >> 5, kk = kidx & 31;
        char* base = reinterpret_cast<char*>(g_AX) + (((size_t)p * NTOK + ar) << 7);
        store_split4(base, ar, kk, accv);
    }
}

// ---------------- launch ------------------------------------------------------
extern "C" void kernel_launch(void* const* d_in, const int* in_sizes, int n_in,
                              void* d_out, int out_size) {
    const float* query = (const float*)d_in[0];
    const float* key   = (const float*)d_in[1];
    const float* value = (const float*)d_in[2];
    const void*  mask  = d_in[3];
    const float* Wq = (const float*)d_in[4];
    const float* bq = (const float*)d_in[5];
    const float* Wk = (const float*)d_in[6];
    const float* bk = (const float*)d_in[7];
    const float* Wv = (const float*)d_in[8];
    const float* bv = (const float*)d_in[9];
    const float* Wo = (const float*)d_in[10];
    const float* bo = (const float*)d_in[11];
    float* out = (float*)d_out;

    cudaFuncSetAttribute(gemm_persist<8, 8, 128>,
                         cudaFuncAttributeMaxDynamicSharedMemorySize, PERSIST_SMEM);
    cudaFuncSetAttribute(gemm_persist<64, 1, 128>,
                         cudaFuncAttributeMaxDynamicSharedMemorySize, PERSIST_SMEM);

    mask_probe<<<1, 32>>>((const unsigned char*)mask);
    split_inputs<<<dim3((NTOK * DMODEL / 4) / 256, 3), 256>>>(
        (const float4*)query, (const float4*)key, (const float4*)value);
    wsplit<<<dim3(64, 64, 4), dim3(32, 8)>>>(Wq, Wk, Wv, Wo);

    bf16 *Aq, *Ak, *Av, *AX, *Bq, *Bk, *Bv, *Bo;
    float *Qp, *Kp, *Vp;
    cudaGetSymbolAddress((void**)&Aq, g_Aq);
    cudaGetSymbolAddress((void**)&Ak, g_Ak);
    cudaGetSymbolAddress((void**)&Av, g_Av);
    cudaGetSymbolAddress((void**)&AX, g_AX);
    cudaGetSymbolAddress((void**)&Bq, g_Bq);
    cudaGetSymbolAddress((void**)&Bk, g_Bk);
    cudaGetSymbolAddress((void**)&Bv, g_Bv);
    cudaGetSymbolAddress((void**)&Bo, g_Bo);
    cudaGetSymbolAddress((void**)&Qp, g_Q);
    cudaGetSymbolAddress((void**)&Kp, g_Kp);
    cudaGetSymbolAddress((void**)&Vp, g_Vp);

    // merged Q/K/V projections: persistent, 3072 jobs over 148 CTAs
    GemmArgs3 qkv;
    qkv.g[0] = { Aq, Bq, bq, Qp };
    qkv.g[1] = { Ak, Bk, bk, Kp };
    qkv.g[2] = { Av, Bv, bv, Vp };
    gemm_persist<8, 8, 128><<<148, 256, PERSIST_SMEM>>>(qkv, 3 * 128 * 8);

    attn_kernel<<<NTOK, 256>>>(mask);

    // output projection: 128 jobs (one per CTA)
    GemmArgs3 oarg;
    oarg.g[0] = { AX, Bo, bo, out };
    oarg.g[1] = oarg.g[0];
    oarg.g[2] = oarg.g[0];
    gemm_persist<64, 1, 128><<<128, 256, PERSIST_SMEM>>>(oarg, 128);
}